// round 1
// baseline (speedup 1.0000x reference)
#include <cuda_runtime.h>
#include <cstddef>

#define ALPHA_ 0.0001f
#define NN 16
#define TT 8
#define VV 256
#define FF 64
#define NVV (NN*VV*VV)

// Zero the two scalar accumulator slots (d_out is poisoned with 0xAA).
__global__ void init_kernel(float* __restrict__ out) {
    if (threadIdx.x == 0) { out[NVV] = 0.f; out[NVV + 1] = 0.f; }
}

// One block per (j-tile of 32 columns, n). 512 threads = 16 warps.
// Warp w handles i in [w*16, w*16+16), lane handles column j = jt*32 + lane.
// Smem holds y = xm * a (a >= 0 so |a*(xi-xj)| == a*|xi-xj|).
extern "C" __global__ void __launch_bounds__(512, 1)
scores_kernel(const float* __restrict__ x, const float* __restrict__ a,
              float* __restrict__ out, int write_scalars) {
    extern __shared__ float y[];        // VV*FF floats = 64 KB
    __shared__ float cs[32];            // per-column exp sums
    __shared__ float wsum[16];          // per-warp S^2 partials

    const int n  = blockIdx.y;
    const int jt = blockIdx.x;          // 0..7
    const float* xm = x + (size_t)(n * TT + TT / 2) * VV * FF;

    if (threadIdx.x < 32) cs[threadIdx.x] = 0.f;

    // Stage y = xm * a into smem (coalesced; a broadcast from L1/L2).
    for (int idx = threadIdx.x; idx < VV * FF; idx += 512)
        y[idx] = xm[idx] * __ldg(&a[idx & (FF - 1)]);
    __syncthreads();

    const int lane  = threadIdx.x & 31;
    const int w     = threadIdx.x >> 5;
    const int j     = jt * 32 + lane;
    const int ibase = w * 16;

    // This thread's column vector, in registers.
    float xj[FF];
#pragma unroll
    for (int f = 0; f < FF; ++f) xj[f] = y[j * FF + f];

    float tmp[16];
    float colpart = 0.f;
#pragma unroll
    for (int g = 0; g < 16; ++g) {
        const float* xi = &y[(ibase + g) * FF];   // broadcast across the warp
        float s0 = 0.f, s1 = 0.f, s2 = 0.f, s3 = 0.f;
#pragma unroll
        for (int f = 0; f < FF; f += 4) {
            s0 += fabsf(xi[f + 0] - xj[f + 0]);
            s1 += fabsf(xi[f + 1] - xj[f + 1]);
            s2 += fabsf(xi[f + 2] - xj[f + 2]);
            s3 += fabsf(xi[f + 3] - xj[f + 3]);
        }
        float sc = (s0 + s1) + (s2 + s3);
        float e  = __expf(fmaxf(sc, 0.f));        // scores >= 0 anyway
        tmp[g] = e;
        colpart += e;
    }

    // Column sums across the 16 warps (32 distinct banks -> spread atomics).
    atomicAdd(&cs[lane], colpart);
    __syncthreads();

    const float inv = 1.0f / cs[lane];

    // Write S (coalesced: per g, warp writes 32 contiguous floats) + accumulate S^2.
    float sq = 0.f;
    float* ocol = out + (size_t)n * VV * VV + jt * 32 + lane;
#pragma unroll
    for (int g = 0; g < 16; ++g) {
        float Sv = tmp[g] * inv;
        ocol[(size_t)(ibase + g) * VV] = Sv;
        sq += Sv * Sv;
    }

#pragma unroll
    for (int o = 16; o; o >>= 1) sq += __shfl_down_sync(0xffffffffu, sq, o);
    if (lane == 0) wsum[w] = sq;
    __syncthreads();
    if (threadIdx.x == 0 && write_scalars) {
        float t = 0.f;
#pragma unroll
        for (int k = 0; k < 16; ++k) t += wsum[k];
        atomicAdd(out + NVV, t * (ALPHA_ / (float)NN));
    }
}

// dloss = ALPHA * sum_{n,f} (2*V*sum_i x^2 - 2*(sum_i x)^2)
// (valid because column sums of S are exactly 1 by construction).
__global__ void __launch_bounds__(64)
dloss_kernel(const float* __restrict__ x, float* __restrict__ out) {
    const int n = blockIdx.x;
    const int f = threadIdx.x;                     // 64 threads = 2 warps
    const float* xm = x + (size_t)(n * TT + TT / 2) * VV * FF;
    float Sx = 0.f, Sq = 0.f;
#pragma unroll 8
    for (int i = 0; i < VV; ++i) {
        float v = xm[(size_t)i * FF + f];
        Sx += v; Sq += v * v;
    }
    float val = 2.f * ((float)VV * Sq - Sx * Sx);
#pragma unroll
    for (int o = 16; o; o >>= 1) val += __shfl_down_sync(0xffffffffu, val, o);
    __shared__ float p[2];
    if ((f & 31) == 0) p[f >> 5] = val;
    __syncthreads();
    if (f == 0) atomicAdd(out + NVV + 1, ALPHA_ * (p[0] + p[1]));
}

extern "C" void kernel_launch(void* const* d_in, const int* in_sizes, int n_in,
                              void* d_out, int out_size) {
    const float* x = (const float*)d_in[0];
    const float* a = (const float*)d_in[1];
    if (n_in >= 2 && in_sizes[0] == FF) {          // defensive input-order check
        const float* t = x; x = a; a = t;
    }
    float* out = (float*)d_out;
    const int write_scalars = (out_size >= NVV + 2) ? 1 : 0;

    cudaFuncSetAttribute(scores_kernel,
                         cudaFuncAttributeMaxDynamicSharedMemorySize,
                         VV * FF * (int)sizeof(float));

    if (write_scalars) init_kernel<<<1, 32>>>(out);
    scores_kernel<<<dim3(8, NN), 512, VV * FF * sizeof(float)>>>(x, a, out, write_scalars);
    if (write_scalars) dloss_kernel<<<NN, 64>>>(x, out);
}

// round 2
// speedup vs baseline: 1.4804x; 1.4804x over previous
#include <cuda_runtime.h>
#include <cstddef>

#define ALPHA_ 0.0001f
#define NN 16
#define TT 8
#define VV 256
#define FF 64
#define NVV (NN*VV*VV)
#define YSTRIDE 68          // 64 + 4 pad: breaks 32-way conflict on column reads
#define NBLK 128

__device__ float g_sloss[NBLK];
__device__ float g_dloss[NN];
__device__ unsigned int g_counter = 0;

__device__ __forceinline__ unsigned long long addx2(unsigned long long a,
                                                    unsigned long long b) {
    unsigned long long r;
    asm("add.rn.f32x2 %0, %1, %2;" : "=l"(r) : "l"(a), "l"(b));
    return r;
}
__device__ __forceinline__ unsigned long long pack2(float lo, float hi) {
    unsigned long long r;
    asm("mov.b64 %0, {%1, %2};" : "=l"(r) : "f"(lo), "f"(hi));
    return r;
}
__device__ __forceinline__ float2 unpack2(unsigned long long v) {
    float2 r;
    asm("mov.b64 {%0, %1}, %2;" : "=f"(r.x), "=f"(r.y) : "l"(v));
    return r;
}

// One block per (j-tile of 32 cols, n): grid (8, 16) = 128 blocks, 512 threads.
// Warp w handles i in [16w, 16w+16), lane handles column j = jt*32 + lane.
extern "C" __global__ void __launch_bounds__(512, 1)
fused_kernel(const float* __restrict__ x, const float* __restrict__ a,
             float* __restrict__ out) {
    extern __shared__ float y[];            // VV * YSTRIDE floats (~68 KB)
    __shared__ float red[512];              // colsum tree
    __shared__ float sxp[512];              // per-thread raw-x sums (dloss)
    __shared__ float sqw[16];
    __shared__ float cs[32];
    __shared__ float wsum[16];
    __shared__ unsigned int s_flag;

    const int tid  = threadIdx.x;
    const int lane = tid & 31;
    const int w    = tid >> 5;
    const int n    = blockIdx.y;
    const int jt   = blockIdx.x;
    const float* __restrict__ xm = x + (size_t)(n * TT + TT / 2) * (VV * FF);

    // Stage y = xm * a into padded smem. Each thread's staging slice has a
    // FIXED feature f = tid & 63, so raw Sx/Sq per-f fall out for free (dloss).
    const int   f  = tid & 63;
    const float af = __ldg(&a[f]);
    float Sx = 0.f, Sq = 0.f;
#pragma unroll
    for (int k = 0; k < 32; ++k) {
        int idx = tid + (k << 9);
        float v = xm[idx];
        y[(idx >> 6) * YSTRIDE + (idx & 63)] = v * af;
        Sx += v;
        Sq = fmaf(v, v, Sq);
    }
    sxp[tid] = Sx;
#pragma unroll
    for (int o = 16; o; o >>= 1) Sq += __shfl_down_sync(~0u, Sq, o);
    if (lane == 0) sqw[w] = Sq;
    __syncthreads();

    // dloss_n = 2*(V*sum x^2 - sum_f (sum_i x)^2); valid because S's column
    // sums are exactly 1 (the softmax axis), so sum(S@d2) = sum(d2).
    // Only the jt==0 block per n computes/writes it (warp 0, no extra sync).
    if (jt == 0 && w == 0) {
        float s1 = 0.f, s2 = 0.f;
#pragma unroll
        for (int r = 0; r < 8; ++r) {
            s1 += sxp[lane + (r << 6)];
            s2 += sxp[lane + 32 + (r << 6)];
        }
        float t  = s1 * s1 + s2 * s2;
        float sq = (lane < 16) ? sqw[lane] : 0.f;
#pragma unroll
        for (int o = 16; o; o >>= 1) {
            t  += __shfl_down_sync(~0u, t, o);
            sq += __shfl_down_sync(~0u, sq, o);
        }
        if (lane == 0) __stcg(&g_dloss[n], 2.f * ((float)VV * sq - t));
    }

    // Negated column j, packed 2-wide (a >= 0 so scale folds into |.|).
    const int j = jt * 32 + lane;
    unsigned long long nxj[32];
#pragma unroll
    for (int q = 0; q < 16; ++q) {
        float4 v = *reinterpret_cast<const float4*>(&y[j * YSTRIDE + q * 4]);
        nxj[2 * q]     = pack2(-v.x, -v.y);
        nxj[2 * q + 1] = pack2(-v.z, -v.w);
    }

    const int ibase = w * 16;
    const unsigned long long M = 0x7fffffff7fffffffULL;
    float tmp[16];
    float colpart = 0.f;
#pragma unroll
    for (int g = 0; g < 16; ++g) {
        const ulonglong2* __restrict__ xi =
            reinterpret_cast<const ulonglong2*>(&y[(ibase + g) * YSTRIDE]);
        unsigned long long a0 = 0, a1 = 0, a2 = 0, a3 = 0;
#pragma unroll
        for (int q = 0; q < 16; q += 2) {
            ulonglong2 p0 = xi[q];               // broadcast LDS.128
            ulonglong2 p1 = xi[q + 1];
            unsigned long long d0 = addx2(p0.x, nxj[2 * q])     & M;  // fma + 2*alu
            unsigned long long d1 = addx2(p0.y, nxj[2 * q + 1]) & M;
            unsigned long long d2 = addx2(p1.x, nxj[2 * q + 2]) & M;
            unsigned long long d3 = addx2(p1.y, nxj[2 * q + 3]) & M;
            a0 = addx2(a0, d0);
            a1 = addx2(a1, d1);
            a2 = addx2(a2, d2);
            a3 = addx2(a3, d3);
        }
        a0 = addx2(a0, a1);
        a2 = addx2(a2, a3);
        a0 = addx2(a0, a2);
        float2 u = unpack2(a0);
        float sc = u.x + u.y;          // scores >= 0 always: relu is identity
        float e  = __expf(sc);
        tmp[g] = e;
        colpart += e;
    }

    // Column sums across the 16 warps (tree, no atomics).
    red[tid] = colpart;
    __syncthreads();
    if (tid < 32) {
        float s = 0.f;
#pragma unroll
        for (int ww = 0; ww < 16; ++ww) s += red[ww * 32 + tid];
        cs[tid] = s;
    }
    __syncthreads();
    const float inv = 1.0f / cs[lane];

    // Write S (coalesced) + accumulate S^2.
    float sq2 = 0.f;
    float* ocol = out + (size_t)n * (VV * VV) + jt * 32 + lane;
#pragma unroll
    for (int g = 0; g < 16; ++g) {
        float Sv = tmp[g] * inv;
        ocol[(size_t)(ibase + g) * VV] = Sv;
        sq2 = fmaf(Sv, Sv, sq2);
    }
#pragma unroll
    for (int o = 16; o; o >>= 1) sq2 += __shfl_down_sync(~0u, sq2, o);
    if (lane == 0) wsum[w] = sq2;
    __syncthreads();

    // Last-block scalar finalize (graph-safe: counter reset every call).
    const int bid = n * 8 + jt;
    if (tid == 0) {
        float t = 0.f;
#pragma unroll
        for (int k = 0; k < 16; ++k) t += wsum[k];
        __stcg(&g_sloss[bid], t);
        __threadfence();
        unsigned int c = atomicAdd(&g_counter, 1u);
        s_flag = (c == NBLK - 1) ? 1u : 0u;
    }
    __syncthreads();
    if (s_flag && w == 0) {
        __threadfence();
        float s = 0.f;
#pragma unroll
        for (int k = 0; k < 4; ++k) s += __ldcg(&g_sloss[lane + (k << 5)]);
        float dl = (lane < 16) ? __ldcg(&g_dloss[lane]) : 0.f;
#pragma unroll
        for (int o = 16; o; o >>= 1) {
            s  += __shfl_down_sync(~0u, s, o);
            dl += __shfl_down_sync(~0u, dl, o);
        }
        if (lane == 0) {
            out[NVV]     = s * (ALPHA_ / (float)NN);
            out[NVV + 1] = dl * ALPHA_;
            g_counter = 0;                 // reset for next graph replay
        }
    }
}

extern "C" void kernel_launch(void* const* d_in, const int* in_sizes, int n_in,
                              void* d_out, int out_size) {
    const float* x = (const float*)d_in[0];
    const float* a = (const float*)d_in[1];
    if (n_in >= 2 && in_sizes[0] == FF) {      // defensive input-order check
        const float* t = x; x = a; a = t;
    }
    float* out = (float*)d_out;

    const int smem = VV * YSTRIDE * (int)sizeof(float);
    cudaFuncSetAttribute(fused_kernel,
                         cudaFuncAttributeMaxDynamicSharedMemorySize, smem);
    fused_kernel<<<dim3(8, NN), 512, smem>>>(x, a, out);
}